// round 5
// baseline (speedup 1.0000x reference)
#include <cuda_runtime.h>
#include <cstdint>

#define KTAG 64
#define BTOT 1024
#define TLEN 512
#define START_TAG 62

// Scratch (allocation-free rule: __device__ globals)
__device__ float g_forward[BTOT];
__device__ float g_goldp[BTOT * 4];

typedef unsigned long long ull;

__device__ __forceinline__ ull pk2(float x, float y) {
    return (ull)__float_as_uint(x) | ((ull)__float_as_uint(y) << 32);
}
__device__ __forceinline__ float lo2(ull v) { return __uint_as_float((unsigned)v); }
__device__ __forceinline__ float hi2(ull v) { return __uint_as_float((unsigned)(v >> 32)); }
__device__ __forceinline__ float rcpf(float x) {
    float r; asm("rcp.approx.f32 %0, %1;" : "=f"(r) : "f"(x)); return r;
}

#define FMA2(acc, a, b) asm("fma.rn.f32x2 %0, %1, %2, %0;" : "+l"(acc) : "l"(a), "l"(b))
#define ADD2(d, a, b)   asm("add.rn.f32x2 %0, %1, %2;" : "=l"(d) : "l"(a), "l"(b))
#define BARN(id)        asm volatile("bar.sync %0, 64;" :: "r"(id) : "memory")

// ---------------------------------------------------------------------------
// Forward kernel, occupancy-first layout.
// CTA = 128 threads = 2 batch rows x 64 tags; ONE tag per lane, so the E-row
// is only 32 f32x2 regs (64 regs) -> ~90 regs/thread -> 5 CTAs/SM (20 warps).
// The 2 warps of a row sync via one named bar.sync(64) per step on a
// double-buffered w vector.
// Invariant: smem buf holds w_j with alpha_{t-1,j} = L + log w_j (L replicated
// per-lane, identical: u = w[0] each step).
// Step: s_i = sum_j E[i,j] w_j (16 LDS.128 + 32 FMA2); w'_i = s_i*exp(f_i)*rcp(u);
//       L += log(u). All MUFU off the critical path (exp(f) prefetched).
// ---------------------------------------------------------------------------
__global__ void __launch_bounds__(128, 5)
crf_forward_kernel(const float* __restrict__ feats,
                   const float* __restrict__ trans) {
    const int i    = threadIdx.x & 63;          // tag index (lane within row)
    const int row  = threadIdx.x >> 6;          // batch row within CTA (0..1)
    const int b    = blockIdx.x * 2 + row;
    const int bar  = 1 + row;                   // named barrier id per row

    __shared__ __align__(16) float sw_[2][2][KTAG];
    __shared__ float szz[2][2];

    // E row for tag i, f32x2-packed over j (64 regs)
    ull E[32];
#pragma unroll
    for (int jj = 0; jj < 32; jj++)
        E[jj] = pk2(__expf(trans[i * KTAG + 2 * jj]),
                    __expf(trans[i * KTAG + 2 * jj + 1]));

    const float* fb = feats + (size_t)b * TLEN * KTAG + i;

    // t = 1 exact: alpha1[i] = trans[i, START] + feat1[i]; w1 = exp(alpha1)
    float a1 = trans[i * KTAG + START_TAG] + fb[1 * KTAG];
    sw_[row][0][i] = __expf(a1);
    float L = 0.0f;

    float fn = fb[2 * KTAG];
    float ef = __expf(fn);
    BARN(bar);

    // main loop: t = 2 .. 510 produce w_t; t = 511 after the loop
    for (int t = 2; t <= TLEN - 2; t++) {
        float efc = ef;
        fn = fb[(size_t)(t + 1) * KTAG];
        ef = __expf(fn);

        const int rbuf = t & 1;
        const ulonglong2* vp = (const ulonglong2*)sw_[row][rbuf];

        ulonglong2 v0 = vp[0];
        float uu = lo2(v0.x);                 // normalizer = w[0] (free)
        float r  = rcpf(uu);                  // parallel with FMA block
        L += __logf(uu);                      // off critical path

        ull c0 = 0, c1 = 0, c2 = 0, c3 = 0;
        FMA2(c0, E[0], v0.x); FMA2(c1, E[1], v0.y);
#pragma unroll
        for (int q = 1; q < 16; q++) {
            ulonglong2 vv = vp[q];            // LDS.128 broadcast
            if (q & 1) { FMA2(c2, E[2 * q], vv.x); FMA2(c3, E[2 * q + 1], vv.y); }
            else       { FMA2(c0, E[2 * q], vv.x); FMA2(c1, E[2 * q + 1], vv.y); }
        }
        ull cA, cB, cs;
        ADD2(cA, c0, c2); ADD2(cB, c1, c3); ADD2(cs, cA, cB);
        float s = lo2(cs) + hi2(cs);

        sw_[row][rbuf ^ 1][i] = s * efc * r;  // STS.32
        BARN(bar);
    }

    // final step t = 511: forward = L + log(sum_i s_i * exp(f_i))
    {
        const int rbuf = (TLEN - 1) & 1;
        const ulonglong2* vp = (const ulonglong2*)sw_[row][rbuf];
        ull c0 = 0, c1 = 0, c2 = 0, c3 = 0;
#pragma unroll
        for (int q = 0; q < 16; q++) {
            ulonglong2 vv = vp[q];
            if (q & 1) { FMA2(c2, E[2 * q], vv.x); FMA2(c3, E[2 * q + 1], vv.y); }
            else       { FMA2(c0, E[2 * q], vv.x); FMA2(c1, E[2 * q + 1], vv.y); }
        }
        ull cA, cB, cs;
        ADD2(cA, c0, c2); ADD2(cB, c1, c3); ADD2(cs, cA, cB);
        float s = lo2(cs) + hi2(cs);

        float z = s * ef;                     // ef = exp(feat[511][i])
#pragma unroll
        for (int o = 16; o > 0; o >>= 1)
            z += __shfl_xor_sync(0xffffffffu, z, o);
        const int half = (threadIdx.x >> 5) & 1;
        if ((threadIdx.x & 31) == 0) szz[row][half] = z;
        BARN(bar);
        if (i == 0) g_forward[b] = L + __logf(szz[row][0] + szz[row][1]);
    }
}

// ---------------------------------------------------------------------------
// Gold-path score: 4 T-segments per batch row, deterministic partials.
// ---------------------------------------------------------------------------
__global__ void __launch_bounds__(256)
crf_gold_kernel(const float* __restrict__ feats,
                const int* __restrict__ tags,
                const float* __restrict__ trans) {
    int gw   = (blockIdx.x * blockDim.x + threadIdx.x) >> 5;
    int lane = threadIdx.x & 31;
    int b    = gw >> 2;
    int seg  = gw & 3;

    const int*   tg  = tags  + (size_t)b * TLEN;
    const float* fbp = feats + (size_t)b * TLEN * KTAG;

    int t0 = seg * (TLEN / 4); if (seg == 0) t0 = 1;
    int t1 = (seg + 1) * (TLEN / 4);

    float s = 0.0f;
    for (int t = t0 + lane; t < t1; t += 32) {
        int ct = tg[t];
        int pt = tg[t - 1];
        s += trans[ct * KTAG + pt] + fbp[(size_t)t * KTAG + ct];
    }
#pragma unroll
    for (int o = 16; o > 0; o >>= 1)
        s += __shfl_xor_sync(0xffffffffu, s, o);
    if (lane == 0) g_goldp[gw] = s;
}

// ---------------------------------------------------------------------------
// Final deterministic reduction: mean(forward - gold) over B.
// ---------------------------------------------------------------------------
__global__ void __launch_bounds__(256)
crf_reduce_kernel(float* __restrict__ out) {
    __shared__ float sh[8];
    int tid  = threadIdx.x;
    int warp = tid >> 5;
    int lane = tid & 31;

    float s = 0.0f;
    for (int x = tid; x < BTOT; x += 256) {
        float g = g_goldp[4 * x] + g_goldp[4 * x + 1] +
                  g_goldp[4 * x + 2] + g_goldp[4 * x + 3];
        s += g_forward[x] - g;
    }
#pragma unroll
    for (int o = 16; o > 0; o >>= 1)
        s += __shfl_xor_sync(0xffffffffu, s, o);
    if (lane == 0) sh[warp] = s;
    __syncthreads();
    if (tid == 0) {
        float tot = 0.0f;
#pragma unroll
        for (int w = 0; w < 8; w++) tot += sh[w];
        out[0] = tot / (float)BTOT;
    }
}

extern "C" void kernel_launch(void* const* d_in, const int* in_sizes, int n_in,
                              void* d_out, int out_size) {
    const float* feats = (const float*)d_in[0];
    const int*   tags  = (const int*)d_in[1];
    const float* trans = (const float*)d_in[2];
    float* out = (float*)d_out;

    // forward first: ncu (-s 5 -c 1) lands on this kernel
    crf_forward_kernel<<<BTOT / 2, 128>>>(feats, trans);
    crf_gold_kernel<<<(BTOT * 4) / 8, 256>>>(feats, tags, trans);
    crf_reduce_kernel<<<1, 256>>>(out);
}

// round 6
// speedup vs baseline: 1.8525x; 1.8525x over previous
#include <cuda_runtime.h>
#include <cstdint>

#define KTAG 64
#define BTOT 1024
#define TLEN 512
#define START_TAG 62

// Scratch (allocation-free rule: __device__ globals)
__device__ float g_forward[BTOT];
__device__ float g_goldp[BTOT * 4];

typedef unsigned long long ull;

__device__ __forceinline__ ull pk2(float x, float y) {
    return (ull)__float_as_uint(x) | ((ull)__float_as_uint(y) << 32);
}
__device__ __forceinline__ float lo2(ull v) { return __uint_as_float((unsigned)v); }
__device__ __forceinline__ float hi2(ull v) { return __uint_as_float((unsigned)(v >> 32)); }
__device__ __forceinline__ float rcpf(float x) {
    float r; asm("rcp.approx.f32 %0, %1;" : "=f"(r) : "f"(x)); return r;
}

#define FMA2(acc, a, b) asm("fma.rn.f32x2 %0, %1, %2, %0;" : "+l"(acc) : "l"(a), "l"(b))
#define ADD2(d, a, b)   asm("add.rn.f32x2 %0, %1, %2;" : "=l"(d) : "l"(a), "l"(b))
#define MUL2(d, a, b)   asm("mul.rn.f32x2 %0, %1, %2;" : "=l"(d) : "l"(a), "l"(b))

// ---------------------------------------------------------------------------
// Forward kernel: R4 layout (1 warp per batch row, 2 tags per lane, E in
// 128 regs) + 4-deep feat prefetch pipeline (MLP=4) so the per-step LDG is
// off the loop-carried critical path.
// Invariant entering step t: smem buf holds w_j with alpha_{t-1,j} = L+log w_j.
// Step: u = w[0] (free, from first LDS.128); s_i = sum_j E[i,j] w_j
//       (16 LDS.128 + 64 FMA2, 8 accumulators); w'_i = s_i*exp(f_t,i)*rcp(u);
//       L += log(u). exp/log/rcp all off the critical path.
// ---------------------------------------------------------------------------
__global__ void __launch_bounds__(128, 2)
crf_forward_kernel(const float* __restrict__ feats,
                   const float* __restrict__ trans) {
    const int lane = threadIdx.x & 31;
    const int w    = threadIdx.x >> 5;          // row within CTA (0..3)
    const int b    = blockIdx.x * 4 + w;
    const int i0   = 2 * lane;
    const int i1   = 2 * lane + 1;

    __shared__ __align__(16) float sw_[4][2][KTAG];

    // E rows for tags i0, i1 (f32x2 packed over j)
    ull E0[32], E1[32];
#pragma unroll
    for (int jj = 0; jj < 32; jj++) {
        E0[jj] = pk2(__expf(trans[i0 * KTAG + 2 * jj]),
                     __expf(trans[i0 * KTAG + 2 * jj + 1]));
        E1[jj] = pk2(__expf(trans[i1 * KTAG + 2 * jj]),
                     __expf(trans[i1 * KTAG + 2 * jj + 1]));
    }

    const float* fb = feats + (size_t)b * TLEN * KTAG;

    // t = 1 exact: alpha1[i] = trans[i, START] + feat1[i]; w1 = exp(alpha1)
    float2 f1 = *(const float2*)(fb + 1 * KTAG + i0);
    float a0 = trans[i0 * KTAG + START_TAG] + f1.x;
    float a1 = trans[i1 * KTAG + START_TAG] + f1.y;
    *(float2*)&sw_[w][0][i0] = make_float2(__expf(a0), __expf(a1));
    float L = 0.0f;

    // 4-deep feat pipeline: F[k] = feat(t = 2+k)
    float2 F[4];
#pragma unroll
    for (int k = 0; k < 4; k++)
        F[k] = *(const float2*)(fb + (size_t)(2 + k) * KTAG + i0);
    __syncwarp();

    // one recurrence step; efc0/efc1 = exp(feat_t) for this step
#define STEP_BODY(T, EFC0, EFC1)                                              \
    {                                                                         \
        const int rbuf = (T) & 1;                                             \
        const ulonglong2* vp = (const ulonglong2*)sw_[w][rbuf];               \
        ulonglong2 v0 = vp[0];                                                \
        float uu = lo2(v0.x);                                                 \
        float r  = rcpf(uu);                                                  \
        L += __logf(uu);                                                      \
        ull c0 = 0, c1 = 0, c2 = 0, c3 = 0;                                   \
        ull d0 = 0, d1 = 0, d2 = 0, d3 = 0;                                   \
        FMA2(c0, E0[0], v0.x); FMA2(c1, E0[1], v0.y);                         \
        FMA2(d0, E1[0], v0.x); FMA2(d1, E1[1], v0.y);                         \
        _Pragma("unroll")                                                     \
        for (int q = 1; q < 16; q++) {                                        \
            ulonglong2 vv = vp[q];                                            \
            if (q & 1) {                                                      \
                FMA2(c2, E0[2 * q], vv.x); FMA2(c3, E0[2 * q + 1], vv.y);     \
                FMA2(d2, E1[2 * q], vv.x); FMA2(d3, E1[2 * q + 1], vv.y);     \
            } else {                                                          \
                FMA2(c0, E0[2 * q], vv.x); FMA2(c1, E0[2 * q + 1], vv.y);     \
                FMA2(d0, E1[2 * q], vv.x); FMA2(d1, E1[2 * q + 1], vv.y);     \
            }                                                                 \
        }                                                                     \
        ull cA, cB, cs, dA, dB, ds, wn, rn;                                   \
        ADD2(cA, c0, c2); ADD2(cB, c1, c3); ADD2(cs, cA, cB);                 \
        ADD2(dA, d0, d2); ADD2(dB, d1, d3); ADD2(ds, dA, dB);                 \
        float s0 = lo2(cs) + hi2(cs);                                         \
        float s1 = lo2(ds) + hi2(ds);                                         \
        rn = pk2((EFC0) * r, (EFC1) * r);                                     \
        MUL2(wn, pk2(s0, s1), rn);                                            \
        *(ull*)&sw_[w][rbuf ^ 1][i0] = wn;                                    \
        __syncwarp();                                                         \
    }

    // main loop: t = 2 .. 509, 127 blocks of 4 (keeps 4 LDGs in flight)
    for (int kb = 0; kb < 127; kb++) {
#pragma unroll
        for (int k = 0; k < 4; k++) {
            const int t = 2 + 4 * kb + k;
            float efc0 = __expf(F[k].x);
            float efc1 = __expf(F[k].y);
            int tn = t + 4; if (tn > TLEN - 1) tn = TLEN - 1;
            F[k] = *(const float2*)(fb + (size_t)tn * KTAG + i0);
            STEP_BODY(t, efc0, efc1)
        }
    }

    // t = 510 (feat in F[0])
    {
        float efc0 = __expf(F[0].x);
        float efc1 = __expf(F[0].y);
        STEP_BODY(510, efc0, efc1)
    }

    // final step t = 511 (feat in F[1]): forward = L + log(sum_i s_i*exp(f_i))
    {
        float ef0 = __expf(F[1].x);
        float ef1 = __expf(F[1].y);
        const int rbuf = (TLEN - 1) & 1;
        const ulonglong2* vp = (const ulonglong2*)sw_[w][rbuf];
        ull c0 = 0, c1 = 0, c2 = 0, c3 = 0;
        ull d0 = 0, d1 = 0, d2 = 0, d3 = 0;
#pragma unroll
        for (int q = 0; q < 16; q++) {
            ulonglong2 vv = vp[q];
            if (q & 1) {
                FMA2(c2, E0[2 * q], vv.x); FMA2(c3, E0[2 * q + 1], vv.y);
                FMA2(d2, E1[2 * q], vv.x); FMA2(d3, E1[2 * q + 1], vv.y);
            } else {
                FMA2(c0, E0[2 * q], vv.x); FMA2(c1, E0[2 * q + 1], vv.y);
                FMA2(d0, E1[2 * q], vv.x); FMA2(d1, E1[2 * q + 1], vv.y);
            }
        }
        ull cA, cB, cs, dA, dB, ds;
        ADD2(cA, c0, c2); ADD2(cB, c1, c3); ADD2(cs, cA, cB);
        ADD2(dA, d0, d2); ADD2(dB, d1, d3); ADD2(ds, dA, dB);
        float s0 = lo2(cs) + hi2(cs);
        float s1 = lo2(ds) + hi2(ds);
        float z = s0 * ef0 + s1 * ef1;
#pragma unroll
        for (int o = 16; o > 0; o >>= 1)
            z += __shfl_xor_sync(0xffffffffu, z, o);
        if (lane == 0) g_forward[b] = L + __logf(z);
    }
#undef STEP_BODY
}

// ---------------------------------------------------------------------------
// Gold-path score: 4 T-segments per batch row, deterministic partials.
// ---------------------------------------------------------------------------
__global__ void __launch_bounds__(256)
crf_gold_kernel(const float* __restrict__ feats,
                const int* __restrict__ tags,
                const float* __restrict__ trans) {
    int gw   = (blockIdx.x * blockDim.x + threadIdx.x) >> 5;
    int lane = threadIdx.x & 31;
    int b    = gw >> 2;
    int seg  = gw & 3;

    const int*   tg  = tags  + (size_t)b * TLEN;
    const float* fbp = feats + (size_t)b * TLEN * KTAG;

    int t0 = seg * (TLEN / 4); if (seg == 0) t0 = 1;
    int t1 = (seg + 1) * (TLEN / 4);

    float s = 0.0f;
    for (int t = t0 + lane; t < t1; t += 32) {
        int ct = tg[t];
        int pt = tg[t - 1];
        s += trans[ct * KTAG + pt] + fbp[(size_t)t * KTAG + ct];
    }
#pragma unroll
    for (int o = 16; o > 0; o >>= 1)
        s += __shfl_xor_sync(0xffffffffu, s, o);
    if (lane == 0) g_goldp[gw] = s;
}

// ---------------------------------------------------------------------------
// Final deterministic reduction: mean(forward - gold) over B.
// ---------------------------------------------------------------------------
__global__ void __launch_bounds__(256)
crf_reduce_kernel(float* __restrict__ out) {
    __shared__ float sh[8];
    int tid  = threadIdx.x;
    int warp = tid >> 5;
    int lane = tid & 31;

    float s = 0.0f;
    for (int x = tid; x < BTOT; x += 256) {
        float g = g_goldp[4 * x] + g_goldp[4 * x + 1] +
                  g_goldp[4 * x + 2] + g_goldp[4 * x + 3];
        s += g_forward[x] - g;
    }
#pragma unroll
    for (int o = 16; o > 0; o >>= 1)
        s += __shfl_xor_sync(0xffffffffu, s, o);
    if (lane == 0) sh[warp] = s;
    __syncthreads();
    if (tid == 0) {
        float tot = 0.0f;
#pragma unroll
        for (int w = 0; w < 8; w++) tot += sh[w];
        out[0] = tot / (float)BTOT;
    }
}

extern "C" void kernel_launch(void* const* d_in, const int* in_sizes, int n_in,
                              void* d_out, int out_size) {
    const float* feats = (const float*)d_in[0];
    const int*   tags  = (const int*)d_in[1];
    const float* trans = (const float*)d_in[2];
    float* out = (float*)d_out;

    // forward first: ncu (-s 5 -c 1) lands on this kernel
    crf_forward_kernel<<<BTOT / 4, 128>>>(feats, trans);
    crf_gold_kernel<<<(BTOT * 4) / 8, 256>>>(feats, tags, trans);
    crf_reduce_kernel<<<1, 256>>>(out);
}